// round 15
// baseline (speedup 1.0000x reference)
#include <cuda_runtime.h>
#include <cuda_fp16.h>
#include <cstdint>

#define BB 8
#define NN 2048
#define FIN 128
#define FOUT 64
#define JSPLIT 8
#define JLEN (NN / JSPLIT)   // 256

// ---- scratch (static device arrays are allowed) ----
__device__ float    g_f1[BB * NN];
__device__ float    g_f2[BB * NN];
// h in MMA B-fragment order: [b][kstep(128)][lane(32)][32 halves] = 2 MB
__device__ __half   g_ht[BB * 128 * 32 * 32];
__device__ unsigned g_adjbit[BB * NN * NN / 32];       // 4 MB bitmask
__device__ float    g_pout[JSPLIT * BB * NN * FOUT];   // 32 MB partial PV sums
__device__ float    g_pden[JSPLIT * BB * NN];          // partial denominators

__device__ __forceinline__ float ex2f(float x) {
    float y; asm("ex2.approx.f32 %0, %1;" : "=f"(y) : "f"(x)); return y;
}
__device__ __forceinline__ float tanhf_hw(float x) {
    float y; asm("tanh.approx.f32 %0, %1;" : "=f"(y) : "f"(x)); return y;
}
// w = exp(tanh(s)) = ex2(tanh(s) * log2(e)).  2 MUFU + 1 MUL, f32-accurate.
__device__ __forceinline__ float gat_w(float s) {
    return ex2f(tanhf_hw(s) * 1.4426950408889634f);
}
__device__ __forceinline__ float eluf(float x) { return x > 0.f ? x : expm1f(x); }
__device__ __forceinline__ uint32_t packh2(float lo, float hi) {
    __half2 h = __floats2half2_rn(lo, hi);
    return *(uint32_t*)&h;
}

// ---------------------------------------------------------------------------
// Kernel A (heterogeneous): 1024 CTAs x 256 thr.
//   even blockIdx -> PROJ role (R13 body): h = x@W, f1/f2; emits h in
//                    B-fragment order (see g_ht layout).
//   odd  blockIdx -> PACK role: adjacency int32 -> bitmask (2048 words/CTA).
// ---------------------------------------------------------------------------
#define HP 40   // hsT pitch in halves

__global__ __launch_bounds__(256) void k_projpack(const float* __restrict__ x,
                                                  const int* __restrict__ adj,
                                                  const float* __restrict__ W,
                                                  const float* __restrict__ a) {
    __shared__ float  Ws[FIN * FOUT];       // 32 KB
    __shared__ __half hsT[FOUT * HP];       // 5 KB

    const int tid  = threadIdx.x;
    const int lane = tid & 31;
    const int warp = tid >> 5;
    const int pid  = blockIdx.x >> 1;

    if (blockIdx.x & 1) {
        // ================= PACK role =================
        const size_t wb  = (size_t)pid * 2048 + warp * 256;
        const int*   src = adj + wb * 32 + lane;
        unsigned*    dst = g_adjbit + wb;

#pragma unroll
        for (int grp = 0; grp < 8; ++grp) {
            unsigned word = 0;
#pragma unroll
            for (int i = 0; i < 32; ++i) {
                const int v = __ldg(src + (size_t)(grp * 32 + i) * 32);
                const unsigned m = __ballot_sync(0xffffffffu, v > 0);
                if (lane == i) word = m;
            }
            dst[grp * 32 + lane] = word;
        }
        return;
    }

    // ================= PROJ role =================
    const int t  = lane & 15;
    const int hh = lane >> 4;
    const int b  = pid >> 6;
    const int jb = (pid & 63) * 32;

    {
        const float4* Wsrc = (const float4*)W;
        float4*       Wdst = (float4*)Ws;
#pragma unroll
        for (int c = 0; c < 8; ++c) Wdst[tid + 256 * c] = Wsrc[tid + 256 * c];
    }
    const float4 av1 = *(const float4*)(a + 4 * t);
    const float4 av2 = *(const float4*)(a + FOUT + 4 * t);
    __syncthreads();

    const float* xr = x + ((size_t)b * NN + jb + warp * 4) * FIN;
    float4 acc[4];
#pragma unroll
    for (int r = 0; r < 4; ++r) acc[r] = make_float4(0.f, 0.f, 0.f, 0.f);

#pragma unroll 4
    for (int k4 = 0; k4 < FIN / 4; ++k4) {
        const int k0 = k4 * 4 + hh * 2;
        float2 xv[4];
#pragma unroll
        for (int r = 0; r < 4; ++r)
            xv[r] = __ldg((const float2*)(xr + (size_t)r * FIN + k0));
        const float4 w0 = *(const float4*)&Ws[k0 * FOUT + 4 * t];
        const float4 w1 = *(const float4*)&Ws[(k0 + 1) * FOUT + 4 * t];
#pragma unroll
        for (int r = 0; r < 4; ++r) {
            acc[r].x = fmaf(xv[r].x, w0.x, acc[r].x);
            acc[r].y = fmaf(xv[r].x, w0.y, acc[r].y);
            acc[r].z = fmaf(xv[r].x, w0.z, acc[r].z);
            acc[r].w = fmaf(xv[r].x, w0.w, acc[r].w);
            acc[r].x = fmaf(xv[r].y, w1.x, acc[r].x);
            acc[r].y = fmaf(xv[r].y, w1.y, acc[r].y);
            acc[r].z = fmaf(xv[r].y, w1.z, acc[r].z);
            acc[r].w = fmaf(xv[r].y, w1.w, acc[r].w);
        }
    }

#pragma unroll
    for (int r = 0; r < 4; ++r) {
        acc[r].x += __shfl_xor_sync(0xffffffffu, acc[r].x, 16);
        acc[r].y += __shfl_xor_sync(0xffffffffu, acc[r].y, 16);
        acc[r].z += __shfl_xor_sync(0xffffffffu, acc[r].z, 16);
        acc[r].w += __shfl_xor_sync(0xffffffffu, acc[r].w, 16);
    }

#pragma unroll
    for (int r = 0; r < 4; ++r) {
        const int rowloc = warp * 4 + r;
        if (hh == 0) {
            hsT[(4 * t) * HP + rowloc]     = __float2half_rn(acc[r].x);
            hsT[(4 * t + 1) * HP + rowloc] = __float2half_rn(acc[r].y);
            hsT[(4 * t + 2) * HP + rowloc] = __float2half_rn(acc[r].z);
            hsT[(4 * t + 3) * HP + rowloc] = __float2half_rn(acc[r].w);
        }
        float p1 = acc[r].x * av1.x + acc[r].y * av1.y
                 + acc[r].z * av1.z + acc[r].w * av1.w;
        float p2 = acc[r].x * av2.x + acc[r].y * av2.y
                 + acc[r].z * av2.z + acc[r].w * av2.w;
#pragma unroll
        for (int d = 8; d; d >>= 1) {
            p1 += __shfl_xor_sync(0xffffffffu, p1, d);
            p2 += __shfl_xor_sync(0xffffffffu, p2, d);
        }
        if (lane == 0) {
            g_f1[b * NN + jb + rowloc] = p1;
            g_f2[b * NN + jb + rowloc] = p2;
        }
    }
    __syncthreads();

    // ---- write-out in B-fragment order ----
    // chunk per thread: ksl = tid>>7, lane_o = (tid&127)>>2, wq = tid&3
    // frag lane (go,to): go = lane_o>>2, to = lane_o&3
    // covers f1 = 16*wq+go, f2 = f1+8, local j base jj0 = ksl*16 + 2*to
    {
        const int ksl    = tid >> 7;
        const int lane_o = (tid & 127) >> 2;
        const int wq     = tid & 3;
        const int go     = lane_o >> 2;
        const int to     = lane_o & 3;
        const int fA     = 16 * wq + go;
        const int fB     = fA + 8;
        const int jj0    = ksl * 16 + 2 * to;

        const uint32_t u0 = *(const uint32_t*)&hsT[fA * HP + jj0];
        const uint32_t u1 = *(const uint32_t*)&hsT[fA * HP + jj0 + 8];
        const uint32_t u2 = *(const uint32_t*)&hsT[fB * HP + jj0];
        const uint32_t u3 = *(const uint32_t*)&hsT[fB * HP + jj0 + 8];

        const int ksg = (pid & 63) * 2 + ksl;   // kstep within batch
        __half* dst = g_ht + (((size_t)(b * 128 + ksg) * 32 + lane_o) * 32 + wq * 8);
        *(uint4*)dst = make_uint4(u0, u1, u2, u3);
    }
}

// ---------------------------------------------------------------------------
// Kernel B: fused GAT attention. Grid (16, 8, 8) = 1024 CTAs; 256 thr.
// Warp owns 16 i x 64 f over a 256-j slice = 16 ksteps. B operands come
// pre-swizzled from g_ht via 4 LDG.128/kstep (L1/L2-resident); NO smem h
// tile, NO cp.async, NO in-loop barriers -> independent warps.
// Denominator via extra MMA against all-ones B.
// ---------------------------------------------------------------------------
#define MPITCH 12            // words per mask row

__global__ __launch_bounds__(256, 4) void k_attn() {
    __shared__ float                  f2s[JLEN];          // 1 KB
    __shared__ __align__(16) unsigned msk[128 * MPITCH];  // 6 KB

    const int tid   = threadIdx.x;
    const int warp  = tid >> 5;
    const int lane  = tid & 31;
    const int t     = lane & 3;
    const int g     = lane >> 2;
    const int b     = blockIdx.z;
    const int split = blockIdx.y;
    const int i0    = blockIdx.x * 128;
    const int jb    = split * JLEN;

    const int rloc0 = warp * 16 + g;
    const int r0    = i0 + rloc0;
    const int r1    = r0 + 8;

    const float f1_0 = g_f1[b * NN + r0];
    const float f1_1 = g_f1[b * NN + r1];
    f2s[tid] = g_f2[b * NN + jb + tid];

    {   // stage masks: 128 rows x 8 words
        const int row  = tid >> 1;
        const int part = tid & 1;
        const uint4 v = *(const uint4*)(g_adjbit +
            ((size_t)b * NN + i0 + row) * (NN / 32) + split * 8 + part * 4);
        *(uint4*)&msk[row * MPITCH + part * 4] = v;
    }
    __syncthreads();

    float acc[32];
#pragma unroll
    for (int k = 0; k < 32; ++k) acc[k] = 0.f;
    float dfrag[4] = {0.f, 0.f, 0.f, 0.f};
    const uint32_t ONES2 = 0x3C003C00u;     // half2(1.0, 1.0)

    // per-lane fragment base for this (b, split): kstep ks = split*16 + ksl
    const uint4* hbase = (const uint4*)g_ht +
        (((size_t)(b * 128 + split * 16) * 32) + lane) * 4;

    for (int ksl = 0; ksl < 16; ++ksl) {
        const uint4* hp = hbase + (size_t)ksl * 128;   // 32 lanes * 4 uint4
        const int s  = ksl >> 1;
        const int kk = ksl & 1;
        const unsigned ua = msk[rloc0 * MPITCH + s] >> (kk * 16 + 2 * t);
        const unsigned ub = msk[(rloc0 + 8) * MPITCH + s] >> (kk * 16 + 2 * t);

        const float2 flo = *(const float2*)&f2s[ksl * 16 + 2 * t];
        const float2 fhi = *(const float2*)&f2s[ksl * 16 + 8 + 2 * t];

        float w00 = gat_w(f1_0 + flo.x), w01 = gat_w(f1_0 + flo.y);
        float w02 = gat_w(f1_0 + fhi.x), w03 = gat_w(f1_0 + fhi.y);
        float w10 = gat_w(f1_1 + flo.x), w11 = gat_w(f1_1 + flo.y);
        float w12 = gat_w(f1_1 + fhi.x), w13 = gat_w(f1_1 + fhi.y);
        w00 = (ua & 1u)     ? w00 : 0.f;
        w01 = (ua & 2u)     ? w01 : 0.f;
        w02 = (ua & 0x100u) ? w02 : 0.f;
        w03 = (ua & 0x200u) ? w03 : 0.f;
        w10 = (ub & 1u)     ? w10 : 0.f;
        w11 = (ub & 2u)     ? w11 : 0.f;
        w12 = (ub & 0x100u) ? w12 : 0.f;
        w13 = (ub & 0x200u) ? w13 : 0.f;

        const uint32_t A0 = packh2(w00, w01);
        const uint32_t A1 = packh2(w10, w11);
        const uint32_t A2 = packh2(w02, w03);
        const uint32_t A3 = packh2(w12, w13);

        // denominator MMA (exact f32 row sums of the quantized weights)
        asm volatile(
            "mma.sync.aligned.m16n8k16.row.col.f32.f16.f16.f32 "
            "{%0,%1,%2,%3}, {%4,%5,%6,%7}, {%8,%9}, {%0,%1,%2,%3};"
            : "+f"(dfrag[0]), "+f"(dfrag[1]), "+f"(dfrag[2]), "+f"(dfrag[3])
            : "r"(A0), "r"(A1), "r"(A2), "r"(A3), "r"(ONES2), "r"(ONES2));

        {   // nb 0..3 from first two uint4
            const uint4 qa = hp[0];
            const uint4 qb = hp[1];
            asm volatile(
                "mma.sync.aligned.m16n8k16.row.col.f32.f16.f16.f32 "
                "{%0,%1,%2,%3}, {%4,%5,%6,%7}, {%8,%9}, {%0,%1,%2,%3};"
                : "+f"(acc[0]), "+f"(acc[1]), "+f"(acc[2]), "+f"(acc[3])
                : "r"(A0), "r"(A1), "r"(A2), "r"(A3), "r"(qa.x), "r"(qa.y));
            asm volatile(
                "mma.sync.aligned.m16n8k16.row.col.f32.f16.f16.f32 "
                "{%0,%1,%2,%3}, {%4,%5,%6,%7}, {%8,%9}, {%0,%1,%2,%3};"
                : "+f"(acc[4]), "+f"(acc[5]), "+f"(acc[6]), "+f"(acc[7])
                : "r"(A0), "r"(A1), "r"(A2), "r"(A3), "r"(qa.z), "r"(qa.w));
            asm volatile(
                "mma.sync.aligned.m16n8k16.row.col.f32.f16.f16.f32 "
                "{%0,%1,%2,%3}, {%4,%5,%6,%7}, {%8,%9}, {%0,%1,%2,%3};"
                : "+f"(acc[8]), "+f"(acc[9]), "+f"(acc[10]), "+f"(acc[11])
                : "r"(A0), "r"(A1), "r"(A2), "r"(A3), "r"(qb.x), "r"(qb.y));
            asm volatile(
                "mma.sync.aligned.m16n8k16.row.col.f32.f16.f16.f32 "
                "{%0,%1,%2,%3}, {%4,%5,%6,%7}, {%8,%9}, {%0,%1,%2,%3};"
                : "+f"(acc[12]), "+f"(acc[13]), "+f"(acc[14]), "+f"(acc[15])
                : "r"(A0), "r"(A1), "r"(A2), "r"(A3), "r"(qb.z), "r"(qb.w));
        }
        {   // nb 4..7 from last two uint4
            const uint4 qc = hp[2];
            const uint4 qd = hp[3];
            asm volatile(
                "mma.sync.aligned.m16n8k16.row.col.f32.f16.f16.f32 "
                "{%0,%1,%2,%3}, {%4,%5,%6,%7}, {%8,%9}, {%0,%1,%2,%3};"
                : "+f"(acc[16]), "+f"(acc[17]), "+f"(acc[18]), "+f"(acc[19])
                : "r"(A0), "r"(A1), "r"(A2), "r"(A3), "r"(qc.x), "r"(qc.y));
            asm volatile(
                "mma.sync.aligned.m16n8k16.row.col.f32.f16.f16.f32 "
                "{%0,%1,%2,%3}, {%4,%5,%6,%7}, {%8,%9}, {%0,%1,%2,%3};"
                : "+f"(acc[20]), "+f"(acc[21]), "+f"(acc[22]), "+f"(acc[23])
                : "r"(A0), "r"(A1), "r"(A2), "r"(A3), "r"(qc.z), "r"(qc.w));
            asm volatile(
                "mma.sync.aligned.m16n8k16.row.col.f32.f16.f16.f32 "
                "{%0,%1,%2,%3}, {%4,%5,%6,%7}, {%8,%9}, {%0,%1,%2,%3};"
                : "+f"(acc[24]), "+f"(acc[25]), "+f"(acc[26]), "+f"(acc[27])
                : "r"(A0), "r"(A1), "r"(A2), "r"(A3), "r"(qd.x), "r"(qd.y));
            asm volatile(
                "mma.sync.aligned.m16n8k16.row.col.f32.f16.f16.f32 "
                "{%0,%1,%2,%3}, {%4,%5,%6,%7}, {%8,%9}, {%0,%1,%2,%3};"
                : "+f"(acc[28]), "+f"(acc[29]), "+f"(acc[30]), "+f"(acc[31])
                : "r"(A0), "r"(A1), "r"(A2), "r"(A3), "r"(qd.z), "r"(qd.w));
        }
    }

    const size_t pbase = (size_t)(split * BB + b);
    if (t == 0) {   // all t hold identical row sums (B was all-ones)
        g_pden[pbase * NN + r0] = dfrag[0];
        g_pden[pbase * NN + r1] = dfrag[2];
    }
    float* o0 = g_pout + (pbase * NN + r0) * FOUT;
    float* o1 = g_pout + (pbase * NN + r1) * FOUT;
#pragma unroll
    for (int nb = 0; nb < 8; ++nb) {
        *(float2*)(o0 + nb * 8 + 2 * t) = make_float2(acc[nb * 4 + 0], acc[nb * 4 + 1]);
        *(float2*)(o1 + nb * 8 + 2 * t) = make_float2(acc[nb * 4 + 2], acc[nb * 4 + 3]);
    }
}

// ---------------------------------------------------------------------------
// Kernel C: combine partials -> divide -> ELU -> out. Memory-bound.
// ---------------------------------------------------------------------------
__global__ __launch_bounds__(256) void k_comb(float* __restrict__ out) {
    const int idx = blockIdx.x * 256 + threadIdx.x;
    const int row = idx >> 4;
    const int seg = idx & 15;

    float den = 0.f;
#pragma unroll
    for (int s = 0; s < JSPLIT; ++s) den += g_pden[(size_t)s * BB * NN + row];
    const float inv = 1.0f / den;

    float4 v = make_float4(0.f, 0.f, 0.f, 0.f);
#pragma unroll
    for (int s = 0; s < JSPLIT; ++s) {
        const float4 p = *(const float4*)(g_pout +
            ((size_t)s * BB * NN + row) * FOUT + seg * 4);
        v.x += p.x; v.y += p.y; v.z += p.z; v.w += p.w;
    }
    v.x = eluf(v.x * inv); v.y = eluf(v.y * inv);
    v.z = eluf(v.z * inv); v.w = eluf(v.w * inv);
    *(float4*)(out + (size_t)row * FOUT + seg * 4) = v;
}

// ---------------------------------------------------------------------------
extern "C" void kernel_launch(void* const* d_in, const int* in_sizes, int n_in,
                              void* d_out, int out_size) {
    const float* x   = (const float*)d_in[0];
    const int*   adj = (const int*)d_in[1];
    const float* W   = (const float*)d_in[2];
    const float* a   = (const float*)d_in[3];
    float*       out = (float*)d_out;

    k_projpack<<<BB * NN / 16, 256>>>(x, adj, W, a);
    k_attn<<<dim3(16, JSPLIT, BB), 256>>>();
    k_comb<<<BB * NN * 16 / 256, 256>>>(out);
}

// round 16
// speedup vs baseline: 1.3138x; 1.3138x over previous
#include <cuda_runtime.h>
#include <cuda_fp16.h>
#include <cstdint>

#define BB 8
#define NN 2048
#define FIN 128
#define FOUT 64
#define JSPLIT 8
#define JLEN (NN / JSPLIT)   // 256

// ---- scratch (static device arrays are allowed) ----
__device__ float    g_f1[BB * NN];
__device__ float    g_f2[BB * NN];
__device__ __half   g_ht[BB * FOUT * NN];              // h^T fp16 [b][f][j]
__device__ unsigned g_adjbit[BB * NN * NN / 32];       // 4 MB bitmask
__device__ float    g_pout[JSPLIT * BB * NN * FOUT];   // 32 MB partial PV sums
__device__ float    g_pden[JSPLIT * BB * NN];          // partial denominators

__device__ __forceinline__ float ex2f(float x) {
    float y; asm("ex2.approx.f32 %0, %1;" : "=f"(y) : "f"(x)); return y;
}
__device__ __forceinline__ float tanhf_hw(float x) {
    float y; asm("tanh.approx.f32 %0, %1;" : "=f"(y) : "f"(x)); return y;
}
// w = exp(tanh(s)) = ex2(tanh(s) * log2(e)).  2 MUFU + 1 MUL, f32-accurate.
__device__ __forceinline__ float gat_w(float s) {
    return ex2f(tanhf_hw(s) * 1.4426950408889634f);
}
__device__ __forceinline__ float eluf(float x) { return x > 0.f ? x : expm1f(x); }
__device__ __forceinline__ uint32_t packh2(float lo, float hi) {
    __half2 h = __floats2half2_rn(lo, hi);
    return *(uint32_t*)&h;
}
__device__ __forceinline__ uint32_t smem_u32(const void* p) {
    uint32_t a;
    asm("{ .reg .u64 t; cvta.to.shared.u64 t, %1; cvt.u32.u64 %0, t; }"
        : "=r"(a) : "l"(p));
    return a;
}
__device__ __forceinline__ void cp16(uint32_t dst, const void* src) {
    asm volatile("cp.async.cg.shared.global [%0], [%1], 16;"
                 :: "r"(dst), "l"(src) : "memory");
}

// ---------------------------------------------------------------------------
// Kernel A (heterogeneous): 1024 CTAs x 256 thr.  (R13 body, measured 33us)
//   even blockIdx -> PROJ role: h = x@W, f1/f2, h^T fp16 [b][f][j].
//   odd  blockIdx -> PACK role: adjacency int32 -> bitmask (2048 words/CTA).
// ---------------------------------------------------------------------------
#define HP 40   // hsT pitch in halves

__global__ __launch_bounds__(256) void k_projpack(const float* __restrict__ x,
                                                  const int* __restrict__ adj,
                                                  const float* __restrict__ W,
                                                  const float* __restrict__ a) {
    __shared__ float  Ws[FIN * FOUT];       // 32 KB
    __shared__ __half hsT[FOUT * HP];       // 5 KB

    const int tid  = threadIdx.x;
    const int lane = tid & 31;
    const int warp = tid >> 5;
    const int pid  = blockIdx.x >> 1;

    if (blockIdx.x & 1) {
        // ================= PACK role =================
        const size_t wb  = (size_t)pid * 2048 + warp * 256;
        const int*   src = adj + wb * 32 + lane;
        unsigned*    dst = g_adjbit + wb;

#pragma unroll
        for (int grp = 0; grp < 8; ++grp) {
            unsigned word = 0;
#pragma unroll
            for (int i = 0; i < 32; ++i) {
                const int v = __ldg(src + (size_t)(grp * 32 + i) * 32);
                const unsigned m = __ballot_sync(0xffffffffu, v > 0);
                if (lane == i) word = m;
            }
            dst[grp * 32 + lane] = word;
        }
        return;
    }

    // ================= PROJ role =================
    const int t  = lane & 15;
    const int hh = lane >> 4;
    const int b  = pid >> 6;
    const int jb = (pid & 63) * 32;

    {
        const float4* Wsrc = (const float4*)W;
        float4*       Wdst = (float4*)Ws;
#pragma unroll
        for (int c = 0; c < 8; ++c) Wdst[tid + 256 * c] = Wsrc[tid + 256 * c];
    }
    const float4 av1 = *(const float4*)(a + 4 * t);
    const float4 av2 = *(const float4*)(a + FOUT + 4 * t);
    __syncthreads();

    const float* xr = x + ((size_t)b * NN + jb + warp * 4) * FIN;
    float4 acc[4];
#pragma unroll
    for (int r = 0; r < 4; ++r) acc[r] = make_float4(0.f, 0.f, 0.f, 0.f);

#pragma unroll 4
    for (int k4 = 0; k4 < FIN / 4; ++k4) {
        const int k0 = k4 * 4 + hh * 2;
        float2 xv[4];
#pragma unroll
        for (int r = 0; r < 4; ++r)
            xv[r] = __ldg((const float2*)(xr + (size_t)r * FIN + k0));
        const float4 w0 = *(const float4*)&Ws[k0 * FOUT + 4 * t];
        const float4 w1 = *(const float4*)&Ws[(k0 + 1) * FOUT + 4 * t];
#pragma unroll
        for (int r = 0; r < 4; ++r) {
            acc[r].x = fmaf(xv[r].x, w0.x, acc[r].x);
            acc[r].y = fmaf(xv[r].x, w0.y, acc[r].y);
            acc[r].z = fmaf(xv[r].x, w0.z, acc[r].z);
            acc[r].w = fmaf(xv[r].x, w0.w, acc[r].w);
            acc[r].x = fmaf(xv[r].y, w1.x, acc[r].x);
            acc[r].y = fmaf(xv[r].y, w1.y, acc[r].y);
            acc[r].z = fmaf(xv[r].y, w1.z, acc[r].z);
            acc[r].w = fmaf(xv[r].y, w1.w, acc[r].w);
        }
    }

#pragma unroll
    for (int r = 0; r < 4; ++r) {
        acc[r].x += __shfl_xor_sync(0xffffffffu, acc[r].x, 16);
        acc[r].y += __shfl_xor_sync(0xffffffffu, acc[r].y, 16);
        acc[r].z += __shfl_xor_sync(0xffffffffu, acc[r].z, 16);
        acc[r].w += __shfl_xor_sync(0xffffffffu, acc[r].w, 16);
    }

#pragma unroll
    for (int r = 0; r < 4; ++r) {
        const int rowloc = warp * 4 + r;
        if (hh == 0) {
            hsT[(4 * t) * HP + rowloc]     = __float2half_rn(acc[r].x);
            hsT[(4 * t + 1) * HP + rowloc] = __float2half_rn(acc[r].y);
            hsT[(4 * t + 2) * HP + rowloc] = __float2half_rn(acc[r].z);
            hsT[(4 * t + 3) * HP + rowloc] = __float2half_rn(acc[r].w);
        }
        float p1 = acc[r].x * av1.x + acc[r].y * av1.y
                 + acc[r].z * av1.z + acc[r].w * av1.w;
        float p2 = acc[r].x * av2.x + acc[r].y * av2.y
                 + acc[r].z * av2.z + acc[r].w * av2.w;
#pragma unroll
        for (int d = 8; d; d >>= 1) {
            p1 += __shfl_xor_sync(0xffffffffu, p1, d);
            p2 += __shfl_xor_sync(0xffffffffu, p2, d);
        }
        if (lane == 0) {
            g_f1[b * NN + jb + rowloc] = p1;
            g_f2[b * NN + jb + rowloc] = p2;
        }
    }
    __syncthreads();

    {
        const int feat = tid >> 2;
        const int seg  = tid & 3;
        const uint4 v = *(const uint4*)&hsT[feat * HP + seg * 8];
        *(uint4*)(g_ht + ((size_t)(b * FOUT + feat)) * NN + jb + seg * 8) = v;
    }
}

// ---------------------------------------------------------------------------
// Kernel B: fused GAT attention. Grid (16, 8, 8) = 1024 CTAs; 256 thr.
// Warp owns 16 i x 64 f over a 256-j slice. The FULL 256-j h^T slice (33 KB)
// is cp.async-staged once in the prologue -> ONE __syncthreads, then a
// completely barrier-free mainloop of 16 independent ksteps per warp.
// Denominator via extra MMA against all-ones B. 4 CTAs/SM.
// ---------------------------------------------------------------------------
#define PITCH 264            // halves per h-row (528 B; lane word = 4g+t, conflict-free)
#define MPITCH 12            // words per mask row

__global__ __launch_bounds__(256, 4) void k_attn() {
    __shared__ float                  f2s[JLEN];            // 1 KB
    __shared__ __align__(16) __half   hTs[FOUT * PITCH];    // 33 KB
    __shared__ __align__(16) unsigned msk[128 * MPITCH];    // 6 KB

    const int tid   = threadIdx.x;
    const int warp  = tid >> 5;
    const int lane  = tid & 31;
    const int t     = lane & 3;
    const int g     = lane >> 2;
    const int b     = blockIdx.z;
    const int split = blockIdx.y;
    const int i0    = blockIdx.x * 128;
    const int jb    = split * JLEN;

    const int rloc0 = warp * 16 + g;
    const int r0    = i0 + rloc0;
    const int r1    = r0 + 8;

    // ---- prologue: stage the whole h^T slice (2048 x 16B chunks, 8/thread) ----
    {
        const uint32_t sb = smem_u32(hTs);
#pragma unroll
        for (int q = 0; q < 8; ++q) {
            const int c    = tid + q * 256;       // 0..2047
            const int feat = c >> 5;
            const int seg  = c & 31;
            cp16(sb + (uint32_t)(feat * PITCH + seg * 8) * 2,
                 g_ht + ((size_t)(b * FOUT + feat)) * NN + jb + seg * 8);
        }
        asm volatile("cp.async.commit_group;" ::: "memory");
    }

    const float f1_0 = g_f1[b * NN + r0];
    const float f1_1 = g_f1[b * NN + r1];
    f2s[tid] = g_f2[b * NN + jb + tid];

    {   // stage masks: 128 rows x 8 words
        const int row  = tid >> 1;
        const int part = tid & 1;
        const uint4 v = *(const uint4*)(g_adjbit +
            ((size_t)b * NN + i0 + row) * (NN / 32) + split * 8 + part * 4);
        *(uint4*)&msk[row * MPITCH + part * 4] = v;
    }

    asm volatile("cp.async.wait_group 0;" ::: "memory");
    __syncthreads();           // the ONLY barrier before the epilogue

    float acc[32];
#pragma unroll
    for (int k = 0; k < 32; ++k) acc[k] = 0.f;
    float dfrag[4] = {0.f, 0.f, 0.f, 0.f};
    const uint32_t ONES2 = 0x3C003C00u;     // half2(1.0, 1.0)

#pragma unroll 2
    for (int ksl = 0; ksl < 16; ++ksl) {
        const int s  = ksl >> 1;
        const int kk = ksl & 1;
        const unsigned ua = msk[rloc0 * MPITCH + s] >> (kk * 16 + 2 * t);
        const unsigned ub = msk[(rloc0 + 8) * MPITCH + s] >> (kk * 16 + 2 * t);

        const float2 flo = *(const float2*)&f2s[ksl * 16 + 2 * t];
        const float2 fhi = *(const float2*)&f2s[ksl * 16 + 8 + 2 * t];

        float w00 = gat_w(f1_0 + flo.x), w01 = gat_w(f1_0 + flo.y);
        float w02 = gat_w(f1_0 + fhi.x), w03 = gat_w(f1_0 + fhi.y);
        float w10 = gat_w(f1_1 + flo.x), w11 = gat_w(f1_1 + flo.y);
        float w12 = gat_w(f1_1 + fhi.x), w13 = gat_w(f1_1 + fhi.y);
        w00 = (ua & 1u)     ? w00 : 0.f;
        w01 = (ua & 2u)     ? w01 : 0.f;
        w02 = (ua & 0x100u) ? w02 : 0.f;
        w03 = (ua & 0x200u) ? w03 : 0.f;
        w10 = (ub & 1u)     ? w10 : 0.f;
        w11 = (ub & 2u)     ? w11 : 0.f;
        w12 = (ub & 0x100u) ? w12 : 0.f;
        w13 = (ub & 0x200u) ? w13 : 0.f;

        const uint32_t A0 = packh2(w00, w01);
        const uint32_t A1 = packh2(w10, w11);
        const uint32_t A2 = packh2(w02, w03);
        const uint32_t A3 = packh2(w12, w13);

        // denominator MMA (exact f32 row sums of the quantized weights)
        asm volatile(
            "mma.sync.aligned.m16n8k16.row.col.f32.f16.f16.f32 "
            "{%0,%1,%2,%3}, {%4,%5,%6,%7}, {%8,%9}, {%0,%1,%2,%3};"
            : "+f"(dfrag[0]), "+f"(dfrag[1]), "+f"(dfrag[2]), "+f"(dfrag[3])
            : "r"(A0), "r"(A1), "r"(A2), "r"(A3), "r"(ONES2), "r"(ONES2));

        const int ko = ksl * 16 + 2 * t;
#pragma unroll
        for (int nb = 0; nb < 8; ++nb) {
            const __half* bp = hTs + (nb * 8 + g) * PITCH + ko;
            const uint32_t B0 = *(const uint32_t*)bp;
            const uint32_t B1 = *(const uint32_t*)(bp + 8);
            float* c = acc + nb * 4;
            asm volatile(
                "mma.sync.aligned.m16n8k16.row.col.f32.f16.f16.f32 "
                "{%0,%1,%2,%3}, {%4,%5,%6,%7}, {%8,%9}, {%0,%1,%2,%3};"
                : "+f"(c[0]), "+f"(c[1]), "+f"(c[2]), "+f"(c[3])
                : "r"(A0), "r"(A1), "r"(A2), "r"(A3), "r"(B0), "r"(B1));
        }
    }

    const size_t pbase = (size_t)(split * BB + b);
    if (t == 0) {   // all t hold identical row sums (B was all-ones)
        g_pden[pbase * NN + r0] = dfrag[0];
        g_pden[pbase * NN + r1] = dfrag[2];
    }
    float* o0 = g_pout + (pbase * NN + r0) * FOUT;
    float* o1 = g_pout + (pbase * NN + r1) * FOUT;
#pragma unroll
    for (int nb = 0; nb < 8; ++nb) {
        *(float2*)(o0 + nb * 8 + 2 * t) = make_float2(acc[nb * 4 + 0], acc[nb * 4 + 1]);
        *(float2*)(o1 + nb * 8 + 2 * t) = make_float2(acc[nb * 4 + 2], acc[nb * 4 + 3]);
    }
}

// ---------------------------------------------------------------------------
// Kernel C: combine partials -> divide -> ELU -> out. Memory-bound.
// ---------------------------------------------------------------------------
__global__ __launch_bounds__(256) void k_comb(float* __restrict__ out) {
    const int idx = blockIdx.x * 256 + threadIdx.x;
    const int row = idx >> 4;
    const int seg = idx & 15;

    float den = 0.f;
#pragma unroll
    for (int s = 0; s < JSPLIT; ++s) den += g_pden[(size_t)s * BB * NN + row];
    const float inv = 1.0f / den;

    float4 v = make_float4(0.f, 0.f, 0.f, 0.f);
#pragma unroll
    for (int s = 0; s < JSPLIT; ++s) {
        const float4 p = *(const float4*)(g_pout +
            ((size_t)s * BB * NN + row) * FOUT + seg * 4);
        v.x += p.x; v.y += p.y; v.z += p.z; v.w += p.w;
    }
    v.x = eluf(v.x * inv); v.y = eluf(v.y * inv);
    v.z = eluf(v.z * inv); v.w = eluf(v.w * inv);
    *(float4*)(out + (size_t)row * FOUT + seg * 4) = v;
}

// ---------------------------------------------------------------------------
extern "C" void kernel_launch(void* const* d_in, const int* in_sizes, int n_in,
                              void* d_out, int out_size) {
    const float* x   = (const float*)d_in[0];
    const int*   adj = (const int*)d_in[1];
    const float* W   = (const float*)d_in[2];
    const float* a   = (const float*)d_in[3];
    float*       out = (float*)d_out;

    k_projpack<<<BB * NN / 16, 256>>>(x, adj, W, a);
    k_attn<<<dim3(16, JSPLIT, BB), 256>>>();
    k_comb<<<BB * NN * 16 / 256, 256>>>(out);
}

// round 17
// speedup vs baseline: 1.3188x; 1.0038x over previous
#include <cuda_runtime.h>
#include <cuda_fp16.h>
#include <cstdint>

#define BB 8
#define NN 2048
#define FIN 128
#define FOUT 64
#define JSPLIT 8
#define JLEN (NN / JSPLIT)   // 256

// ---- scratch (static device arrays are allowed) ----
__device__ float    g_f1[BB * NN];
__device__ float    g_f2[BB * NN];
__device__ __half   g_ht[BB * FOUT * NN];              // h^T fp16 [b][f][j]
__device__ unsigned g_adjbit[BB * NN * NN / 32];       // 4 MB bitmask
__device__ float    g_pout[JSPLIT * BB * NN * FOUT];   // 32 MB partial PV sums
__device__ float    g_pden[JSPLIT * BB * NN];          // partial denominators

__device__ __forceinline__ float eluf(float x) { return x > 0.f ? x : expm1f(x); }
__device__ __forceinline__ uint32_t smem_u32(const void* p) {
    uint32_t a;
    asm("{ .reg .u64 t; cvta.to.shared.u64 t, %1; cvt.u32.u64 %0, t; }"
        : "=r"(a) : "l"(p));
    return a;
}
__device__ __forceinline__ void cp16(uint32_t dst, const void* src) {
    asm volatile("cp.async.cg.shared.global [%0], [%1], 16;"
                 :: "r"(dst), "l"(src) : "memory");
}

// Two scores at once: w = exp(tanh(s)) = ex2(tanh(s)*log2e) on the f16x2
// MUFU path (2 MUFU per score PAIR). s computed in f32 (cancellation-safe),
// packed, then tanh/ex2 in f16x2. Output is the pre-masked A-fragment word.
__device__ __forceinline__ uint32_t score2(float s_lo, float s_hi, uint32_t mask) {
    __half2 p = __floats2half2_rn(s_lo, s_hi);
    uint32_t pu = *(uint32_t*)&p;
    uint32_t th;
    asm("tanh.approx.f16x2 %0, %1;" : "=r"(th) : "r"(pu));
    const __half2 L2E = __floats2half2_rn(1.4426950408889634f, 1.4426950408889634f);
    __half2 sc = __hmul2(*(const __half2*)&th, L2E);
    uint32_t scu = *(uint32_t*)&sc;
    uint32_t w;
    asm("ex2.approx.f16x2 %0, %1;" : "=r"(w) : "r"(scu));
    return w & mask;
}
// expand adjacency bits (positions p, p+1 of u) into an f16x2 keep-mask
__device__ __forceinline__ uint32_t bits2mask(uint32_t u, int p) {
    return ((u >> p) & 1u) * 0x0000FFFFu + (((u >> p) & 2u) >> 1) * 0xFFFF0000u;
}

// ---------------------------------------------------------------------------
// Kernel A (heterogeneous): 1024 CTAs x 256 thr.  (R13 body, measured ~33us)
//   even blockIdx -> PROJ role: h = x@W, f1/f2, h^T fp16 [b][f][j].
//   odd  blockIdx -> PACK role: adjacency int32 -> bitmask (2048 words/CTA).
// ---------------------------------------------------------------------------
#define HP 40   // hsT pitch in halves

__global__ __launch_bounds__(256) void k_projpack(const float* __restrict__ x,
                                                  const int* __restrict__ adj,
                                                  const float* __restrict__ W,
                                                  const float* __restrict__ a) {
    __shared__ float  Ws[FIN * FOUT];       // 32 KB
    __shared__ __half hsT[FOUT * HP];       // 5 KB

    const int tid  = threadIdx.x;
    const int lane = tid & 31;
    const int warp = tid >> 5;
    const int pid  = blockIdx.x >> 1;

    if (blockIdx.x & 1) {
        // ================= PACK role =================
        const size_t wb  = (size_t)pid * 2048 + warp * 256;
        const int*   src = adj + wb * 32 + lane;
        unsigned*    dst = g_adjbit + wb;

#pragma unroll
        for (int grp = 0; grp < 8; ++grp) {
            unsigned word = 0;
#pragma unroll
            for (int i = 0; i < 32; ++i) {
                const int v = __ldg(src + (size_t)(grp * 32 + i) * 32);
                const unsigned m = __ballot_sync(0xffffffffu, v > 0);
                if (lane == i) word = m;
            }
            dst[grp * 32 + lane] = word;
        }
        return;
    }

    // ================= PROJ role =================
    const int t  = lane & 15;
    const int hh = lane >> 4;
    const int b  = pid >> 6;
    const int jb = (pid & 63) * 32;

    {
        const float4* Wsrc = (const float4*)W;
        float4*       Wdst = (float4*)Ws;
#pragma unroll
        for (int c = 0; c < 8; ++c) Wdst[tid + 256 * c] = Wsrc[tid + 256 * c];
    }
    const float4 av1 = *(const float4*)(a + 4 * t);
    const float4 av2 = *(const float4*)(a + FOUT + 4 * t);
    __syncthreads();

    const float* xr = x + ((size_t)b * NN + jb + warp * 4) * FIN;
    float4 acc[4];
#pragma unroll
    for (int r = 0; r < 4; ++r) acc[r] = make_float4(0.f, 0.f, 0.f, 0.f);

#pragma unroll 4
    for (int k4 = 0; k4 < FIN / 4; ++k4) {
        const int k0 = k4 * 4 + hh * 2;
        float2 xv[4];
#pragma unroll
        for (int r = 0; r < 4; ++r)
            xv[r] = __ldg((const float2*)(xr + (size_t)r * FIN + k0));
        const float4 w0 = *(const float4*)&Ws[k0 * FOUT + 4 * t];
        const float4 w1 = *(const float4*)&Ws[(k0 + 1) * FOUT + 4 * t];
#pragma unroll
        for (int r = 0; r < 4; ++r) {
            acc[r].x = fmaf(xv[r].x, w0.x, acc[r].x);
            acc[r].y = fmaf(xv[r].x, w0.y, acc[r].y);
            acc[r].z = fmaf(xv[r].x, w0.z, acc[r].z);
            acc[r].w = fmaf(xv[r].x, w0.w, acc[r].w);
            acc[r].x = fmaf(xv[r].y, w1.x, acc[r].x);
            acc[r].y = fmaf(xv[r].y, w1.y, acc[r].y);
            acc[r].z = fmaf(xv[r].y, w1.z, acc[r].z);
            acc[r].w = fmaf(xv[r].y, w1.w, acc[r].w);
        }
    }

#pragma unroll
    for (int r = 0; r < 4; ++r) {
        acc[r].x += __shfl_xor_sync(0xffffffffu, acc[r].x, 16);
        acc[r].y += __shfl_xor_sync(0xffffffffu, acc[r].y, 16);
        acc[r].z += __shfl_xor_sync(0xffffffffu, acc[r].z, 16);
        acc[r].w += __shfl_xor_sync(0xffffffffu, acc[r].w, 16);
    }

#pragma unroll
    for (int r = 0; r < 4; ++r) {
        const int rowloc = warp * 4 + r;
        if (hh == 0) {
            hsT[(4 * t) * HP + rowloc]     = __float2half_rn(acc[r].x);
            hsT[(4 * t + 1) * HP + rowloc] = __float2half_rn(acc[r].y);
            hsT[(4 * t + 2) * HP + rowloc] = __float2half_rn(acc[r].z);
            hsT[(4 * t + 3) * HP + rowloc] = __float2half_rn(acc[r].w);
        }
        float p1 = acc[r].x * av1.x + acc[r].y * av1.y
                 + acc[r].z * av1.z + acc[r].w * av1.w;
        float p2 = acc[r].x * av2.x + acc[r].y * av2.y
                 + acc[r].z * av2.z + acc[r].w * av2.w;
#pragma unroll
        for (int d = 8; d; d >>= 1) {
            p1 += __shfl_xor_sync(0xffffffffu, p1, d);
            p2 += __shfl_xor_sync(0xffffffffu, p2, d);
        }
        if (lane == 0) {
            g_f1[b * NN + jb + rowloc] = p1;
            g_f2[b * NN + jb + rowloc] = p2;
        }
    }
    __syncthreads();

    {
        const int feat = tid >> 2;
        const int seg  = tid & 3;
        const uint4 v = *(const uint4*)&hsT[feat * HP + seg * 8];
        *(uint4*)(g_ht + ((size_t)(b * FOUT + feat)) * NN + jb + seg * 8) = v;
    }
}

// ---------------------------------------------------------------------------
// Kernel B: fused GAT attention. Grid (16, 8, 8) = 1024 CTAs; 256 thr.
// Warp owns 16 i x 64 f over a 256-j slice. FULL 256-j h^T slice (33 KB)
// cp.async-staged once -> ONE barrier, then a barrier-free mainloop of 16
// independent ksteps. Scores on the f16x2 MUFU path (2 MUFU per score pair);
// denominator via extra MMA against all-ones B. 4 CTAs/SM.
// ---------------------------------------------------------------------------
#define PITCH 264            // halves per h-row (528 B; lane word = 4g+t, conflict-free)
#define MPITCH 12            // words per mask row

__global__ __launch_bounds__(256, 4) void k_attn() {
    __shared__ float                  f2s[JLEN];            // 1 KB
    __shared__ __align__(16) __half   hTs[FOUT * PITCH];    // 33 KB
    __shared__ __align__(16) unsigned msk[128 * MPITCH];    // 6 KB

    const int tid   = threadIdx.x;
    const int warp  = tid >> 5;
    const int lane  = tid & 31;
    const int t     = lane & 3;
    const int g     = lane >> 2;
    const int b     = blockIdx.z;
    const int split = blockIdx.y;
    const int i0    = blockIdx.x * 128;
    const int jb    = split * JLEN;

    const int rloc0 = warp * 16 + g;
    const int r0    = i0 + rloc0;
    const int r1    = r0 + 8;

    // ---- prologue: stage the whole h^T slice (2048 x 16B chunks, 8/thread) ----
    {
        const uint32_t sb = smem_u32(hTs);
#pragma unroll
        for (int q = 0; q < 8; ++q) {
            const int c    = tid + q * 256;       // 0..2047
            const int feat = c >> 5;
            const int seg  = c & 31;
            cp16(sb + (uint32_t)(feat * PITCH + seg * 8) * 2,
                 g_ht + ((size_t)(b * FOUT + feat)) * NN + jb + seg * 8);
        }
        asm volatile("cp.async.commit_group;" ::: "memory");
    }

    const float f1_0 = g_f1[b * NN + r0];
    const float f1_1 = g_f1[b * NN + r1];
    f2s[tid] = g_f2[b * NN + jb + tid];

    {   // stage masks: 128 rows x 8 words
        const int row  = tid >> 1;
        const int part = tid & 1;
        const uint4 v = *(const uint4*)(g_adjbit +
            ((size_t)b * NN + i0 + row) * (NN / 32) + split * 8 + part * 4);
        *(uint4*)&msk[row * MPITCH + part * 4] = v;
    }

    asm volatile("cp.async.wait_group 0;" ::: "memory");
    __syncthreads();           // the ONLY barrier before the epilogue

    float acc[32];
#pragma unroll
    for (int k = 0; k < 32; ++k) acc[k] = 0.f;
    float dfrag[4] = {0.f, 0.f, 0.f, 0.f};
    const uint32_t ONES2 = 0x3C003C00u;     // half2(1.0, 1.0)

#pragma unroll 2
    for (int ksl = 0; ksl < 16; ++ksl) {
        const int s  = ksl >> 1;
        const int kk = ksl & 1;
        const unsigned ua = msk[rloc0 * MPITCH + s] >> (kk * 16 + 2 * t);
        const unsigned ub = msk[(rloc0 + 8) * MPITCH + s] >> (kk * 16 + 2 * t);

        const float2 flo = *(const float2*)&f2s[ksl * 16 + 2 * t];
        const float2 fhi = *(const float2*)&f2s[ksl * 16 + 8 + 2 * t];

        const uint32_t A0 = score2(f1_0 + flo.x, f1_0 + flo.y, bits2mask(ua, 0));
        const uint32_t A1 = score2(f1_1 + flo.x, f1_1 + flo.y, bits2mask(ub, 0));
        const uint32_t A2 = score2(f1_0 + fhi.x, f1_0 + fhi.y, bits2mask(ua, 8));
        const uint32_t A3 = score2(f1_1 + fhi.x, f1_1 + fhi.y, bits2mask(ub, 8));

        // denominator MMA (exact f32 row sums of the quantized weights)
        asm volatile(
            "mma.sync.aligned.m16n8k16.row.col.f32.f16.f16.f32 "
            "{%0,%1,%2,%3}, {%4,%5,%6,%7}, {%8,%9}, {%0,%1,%2,%3};"
            : "+f"(dfrag[0]), "+f"(dfrag[1]), "+f"(dfrag[2]), "+f"(dfrag[3])
            : "r"(A0), "r"(A1), "r"(A2), "r"(A3), "r"(ONES2), "r"(ONES2));

        const int ko = ksl * 16 + 2 * t;
#pragma unroll
        for (int nb = 0; nb < 8; ++nb) {
            const __half* bp = hTs + (nb * 8 + g) * PITCH + ko;
            const uint32_t B0 = *(const uint32_t*)bp;
            const uint32_t B1 = *(const uint32_t*)(bp + 8);
            float* c = acc + nb * 4;
            asm volatile(
                "mma.sync.aligned.m16n8k16.row.col.f32.f16.f16.f32 "
                "{%0,%1,%2,%3}, {%4,%5,%6,%7}, {%8,%9}, {%0,%1,%2,%3};"
                : "+f"(c[0]), "+f"(c[1]), "+f"(c[2]), "+f"(c[3])
                : "r"(A0), "r"(A1), "r"(A2), "r"(A3), "r"(B0), "r"(B1));
        }
    }

    const size_t pbase = (size_t)(split * BB + b);
    if (t == 0) {   // all t hold identical row sums (B was all-ones)
        g_pden[pbase * NN + r0] = dfrag[0];
        g_pden[pbase * NN + r1] = dfrag[2];
    }
    float* o0 = g_pout + (pbase * NN + r0) * FOUT;
    float* o1 = g_pout + (pbase * NN + r1) * FOUT;
#pragma unroll
    for (int nb = 0; nb < 8; ++nb) {
        *(float2*)(o0 + nb * 8 + 2 * t) = make_float2(acc[nb * 4 + 0], acc[nb * 4 + 1]);
        *(float2*)(o1 + nb * 8 + 2 * t) = make_float2(acc[nb * 4 + 2], acc[nb * 4 + 3]);
    }
}

// ---------------------------------------------------------------------------
// Kernel C: combine partials -> divide -> ELU -> out. Memory-bound.
// ---------------------------------------------------------------------------
__global__ __launch_bounds__(256) void k_comb(float* __restrict__ out) {
    const int idx = blockIdx.x * 256 + threadIdx.x;
    const int row = idx >> 4;
    const int seg = idx & 15;

    float den = 0.f;
#pragma unroll
    for (int s = 0; s < JSPLIT; ++s) den += g_pden[(size_t)s * BB * NN + row];
    const float inv = 1.0f / den;

    float4 v = make_float4(0.f, 0.f, 0.f, 0.f);
#pragma unroll
    for (int s = 0; s < JSPLIT; ++s) {
        const float4 p = *(const float4*)(g_pout +
            ((size_t)s * BB * NN + row) * FOUT + seg * 4);
        v.x += p.x; v.y += p.y; v.z += p.z; v.w += p.w;
    }
    v.x = eluf(v.x * inv); v.y = eluf(v.y * inv);
    v.z = eluf(v.z * inv); v.w = eluf(v.w * inv);
    *(float4*)(out + (size_t)row * FOUT + seg * 4) = v;
}

// ---------------------------------------------------------------------------
extern "C" void kernel_launch(void* const* d_in, const int* in_sizes, int n_in,
                              void* d_out, int out_size) {
    const float* x   = (const float*)d_in[0];
    const int*   adj = (const int*)d_in[1];
    const float* W   = (const float*)d_in[2];
    const float* a   = (const float*)d_in[3];
    float*       out = (float*)d_out;

    k_projpack<<<BB * NN / 16, 256>>>(x, adj, W, a);
    k_attn<<<dim3(16, JSPLIT, BB), 256>>>();
    k_comb<<<BB * NN * 16 / 256, 256>>>(out);
}